// round 12
// baseline (speedup 1.0000x reference)
#include <cuda_runtime.h>

#define BB 512
#define TT 256

typedef unsigned long long u64;

// Inter-layer hidden sequences, batch-major [B, T, H]. Max H=256 -> 128 MB each.
__device__ float g_bufA[BB * TT * 256];
__device__ float g_bufB[BB * TT * 256];

__device__ __forceinline__ void ffma2(u64& d, u64 a, u64 b) {
    // packed fp32x2 fma: d.lo += a.lo*b.lo ; d.hi += a.hi*b.hi (IEEE per lane)
    asm("fma.rn.f32x2 %0, %1, %2, %0;" : "+l"(d) : "l"(a), "l"(b));
}
__device__ __forceinline__ u64 dup2(float w) {
    // (w, w) packed pair; MOVs ride a parallel pipe to the fma pipe
    u64 r;
    unsigned int wu = __float_as_uint(w);
    asm("mov.b64 %0, {%1, %1};" : "=l"(r) : "r"(wu));
    return r;
}

// ============================================================================
// SCALAR kernel (latency-friendly; measured-best for L1/L3/L4).
// Thread (j, p) owns output column j and p-th k-slice; KREG weights in regs,
// KSM rows in dynamic smem. Acts k-major float4 (r0..r3); inner loop =
// 1 uniform LDS.128 + 4 FFMA per k.
// ============================================================================
template<int FIN, int H, int P, int KREG, int THREADS, bool FUSE_DENSE>
__global__ void __launch_bounds__(THREADS, 1)
rnn_layer(const float* __restrict__ x, const float* __restrict__ Wx,
          const float* __restrict__ Wh, const float* __restrict__ bias,
          float* __restrict__ hout, const float* __restrict__ Wd,
          const float* __restrict__ bd, float* __restrict__ out)
{
    constexpr int BT  = 4;
    constexpr int KV  = FIN + H;
    constexpr int KS  = KV / P;
    constexpr int KSM = KS - KREG;
    constexpr int CNT  = (BT * H + THREADS - 1) / THREADS;
    constexpr int CNTX = (BT * FIN + THREADS - 1) / THREADS;
    constexpr int REDN = FUSE_DENSE ? THREADS : 1;
    static_assert(H * P == THREADS, "thread count");
    static_assert(KV % P == 0 && KSM >= 0, "k partition");
    static_assert(!FUSE_DENSE || CNT == 1, "dense fusion assumes CNT==1");

    extern __shared__ float ws[];                       // [P][KSM][H]
    __shared__ __align__(16) float4 buf[2][KV];
    __shared__ float part[(P > 1 ? P : 1)][BT][(P > 1 ? H : 1)];
    __shared__ float red[REDN];

    const int tid = threadIdx.x;
    const int j   = tid % H;
    const int p   = tid / H;
    const int b0  = blockIdx.x * BT;
    const int k0  = p * KS;

    float w[KREG > 0 ? KREG : 1];
    #pragma unroll
    for (int q = 0; q < KREG; ++q) {
        int v = k0 + q;
        w[q] = (v < FIN) ? __ldg(&Wx[v * H + j]) : __ldg(&Wh[(v - FIN) * H + j]);
    }
    if (KSM > 0) {
        for (int idx = tid; idx < P * KSM * H; idx += THREADS) {
            int pp = idx / (KSM * H);
            int rem = idx % (KSM * H);
            int s = rem / H, jj = rem % H;
            int v = pp * KS + KREG + s;
            ws[idx] = (v < FIN) ? Wx[v * H + jj] : Wh[(v - FIN) * H + jj];
        }
    }
    for (int i = tid; i < H; i += THREADS) buf[0][FIN + i] = make_float4(0.f, 0.f, 0.f, 0.f);
    #pragma unroll
    for (int q = 0; q < CNTX; ++q) {
        int i = tid + q * THREADS;
        if (i < BT * FIN) {
            int r = i / FIN, k = i % FIN;
            ((float*)buf[0])[k * 4 + r] = __ldcg(&x[((b0 + r) * TT + 0) * FIN + k]);
        }
    }

    const float bjj = bias[j];
    float bj[CNT];
    #pragma unroll
    for (int q = 0; q < CNT; ++q) {
        int e = tid + q * THREADS;
        bj[q] = (e < BT * H) ? bias[e % H] : 0.f;
    }

    __syncthreads();

    float dacc = 0.f;
    int cb = 0;

    for (int t = 0; t < TT; ++t) {
        const int nb = cb ^ 1;

        float xst[CNTX];
        if (t + 1 < TT) {
            #pragma unroll
            for (int q = 0; q < CNTX; ++q) {
                int i = tid + q * THREADS;
                if (i < BT * FIN)
                    xst[q] = __ldcg(&x[((b0 + i / FIN) * TT + (t + 1)) * FIN + (i % FIN)]);
            }
        }

        float a0 = 0.f, a1 = 0.f, a2 = 0.f, a3 = 0.f;
        const float4* ub = buf[cb] + k0;

        #pragma unroll
        for (int q = 0; q < KREG; ++q) {
            float4 v = ub[q];
            a0 = fmaf(v.x, w[q], a0);
            a1 = fmaf(v.y, w[q], a1);
            a2 = fmaf(v.z, w[q], a2);
            a3 = fmaf(v.w, w[q], a3);
        }
        if (KSM > 0) {
            const float* wsp = ws + (p * KSM) * H + j;
            #pragma unroll 8
            for (int s = 0; s < KSM; ++s) {
                float4 v = ub[KREG + s];
                float wv = wsp[s * H];
                a0 = fmaf(v.x, wv, a0);
                a1 = fmaf(v.y, wv, a1);
                a2 = fmaf(v.z, wv, a2);
                a3 = fmaf(v.w, wv, a3);
            }
        }

        if (P == 1) {
            float4 hv;
            hv.x = fmaxf(a0 + bjj, 0.f);
            hv.y = fmaxf(a1 + bjj, 0.f);
            hv.z = fmaxf(a2 + bjj, 0.f);
            hv.w = fmaxf(a3 + bjj, 0.f);
            buf[nb][FIN + j] = hv;
            if (t + 1 < TT) {
                #pragma unroll
                for (int q = 0; q < CNTX; ++q) {
                    int i = tid + q * THREADS;
                    if (i < BT * FIN)
                        ((float*)buf[nb])[(i % FIN) * 4 + (i / FIN)] = xst[q];
                }
            }
            __stcg(&hout[((b0 + 0) * TT + t) * H + j], hv.x);
            __stcg(&hout[((b0 + 1) * TT + t) * H + j], hv.y);
            __stcg(&hout[((b0 + 2) * TT + t) * H + j], hv.z);
            __stcg(&hout[((b0 + 3) * TT + t) * H + j], hv.w);
            __syncthreads();
        } else {
            part[p][0][j] = a0;
            part[p][1][j] = a1;
            part[p][2][j] = a2;
            part[p][3][j] = a3;
            if (t + 1 < TT) {
                #pragma unroll
                for (int q = 0; q < CNTX; ++q) {
                    int i = tid + q * THREADS;
                    if (i < BT * FIN)
                        ((float*)buf[nb])[(i % FIN) * 4 + (i / FIN)] = xst[q];
                }
            }
            __syncthreads();
            #pragma unroll
            for (int q = 0; q < CNT; ++q) {
                int e = tid + q * THREADS;
                if (e < BT * H) {
                    int r = e / H, jj = e % H;
                    float s = bj[q];
                    #pragma unroll
                    for (int pp = 0; pp < P; ++pp) s += part[pp][r][jj];
                    s = fmaxf(s, 0.f);
                    ((float*)buf[nb])[(FIN + jj) * 4 + r] = s;
                    if (FUSE_DENSE) {
                        dacc = fmaf(s, __ldg(&Wd[t * H + jj]), dacc);
                    } else {
                        __stcg(&hout[((b0 + r) * TT + t) * H + jj], s);
                    }
                }
            }
            __syncthreads();
        }
        cb = nb;
    }

    if (FUSE_DENSE) {
        red[tid] = dacc;
        __syncthreads();
        if (tid < BT) {
            float s = bd[0];
            #pragma unroll 8
            for (int q = 0; q < H; ++q) s += red[tid * H + q];
            out[b0 + tid] = s;
        }
    }
}

// ============================================================================
// MOVDUP-FFMA2 kernel for layer 2 (the FFMA-pipe-bound layer), now with
// P-way k-split so THREADS = H*P = 512 -> 4 warps/SMSP for latency hiding.
// Storage layout = scalar (KREG scalar weight regs, KSM scalar smem rows,
// non-duplicated float4 acts). Inner loop per k: LDS.128 act pair-of-pairs,
// mov.b64 {w,w} (parallel pipe), 2 FFMA2. Partials combined P-way.
// ============================================================================
template<int FIN, int H, int P, int KREG, int THREADS>
__global__ void __launch_bounds__(THREADS, 1)
rnn_layer_md(const float* __restrict__ x, const float* __restrict__ Wx,
             const float* __restrict__ Wh, const float* __restrict__ bias,
             float* __restrict__ hout)
{
    constexpr int BT  = 4;
    constexpr int KV  = FIN + H;
    constexpr int KS  = KV / P;
    constexpr int KSM = KS - KREG;
    constexpr int CNT  = (BT * H + THREADS - 1) / THREADS;
    constexpr int CNTX = (BT * FIN + THREADS - 1) / THREADS;
    static_assert(H * P == THREADS, "thread count");
    static_assert(KV % P == 0 && KSM >= 0, "k partition");

    extern __shared__ float ws[];                       // [P][KSM][H]
    __shared__ __align__(16) float4 buf[2][KV];
    __shared__ float part[P][BT][H];

    const int tid = threadIdx.x;
    const int j   = tid % H;
    const int p   = tid / H;
    const int b0  = blockIdx.x * BT;
    const int k0  = p * KS;

    float w[KREG];
    #pragma unroll
    for (int q = 0; q < KREG; ++q) {
        int v = k0 + q;
        w[q] = (v < FIN) ? __ldg(&Wx[v * H + j]) : __ldg(&Wh[(v - FIN) * H + j]);
    }
    if (KSM > 0) {
        for (int idx = tid; idx < P * KSM * H; idx += THREADS) {
            int pp = idx / (KSM * H);
            int rem = idx % (KSM * H);
            int s = rem / H, jj = rem % H;
            int v = pp * KS + KREG + s;
            ws[idx] = (v < FIN) ? Wx[v * H + jj] : Wh[(v - FIN) * H + jj];
        }
    }
    for (int i = tid; i < H; i += THREADS) buf[0][FIN + i] = make_float4(0.f, 0.f, 0.f, 0.f);
    #pragma unroll
    for (int q = 0; q < CNTX; ++q) {
        int i = tid + q * THREADS;
        if (i < BT * FIN) {
            int r = i / FIN, k = i % FIN;
            ((float*)buf[0])[k * 4 + r] = __ldcg(&x[((b0 + r) * TT + 0) * FIN + k]);
        }
    }
    float bj[CNT];
    #pragma unroll
    for (int q = 0; q < CNT; ++q) {
        int e = tid + q * THREADS;
        bj[q] = (e < BT * H) ? bias[e % H] : 0.f;
    }

    __syncthreads();

    int cb = 0;

    for (int t = 0; t < TT; ++t) {
        const int nb = cb ^ 1;

        float xst[CNTX];
        if (t + 1 < TT) {
            #pragma unroll
            for (int q = 0; q < CNTX; ++q) {
                int i = tid + q * THREADS;
                if (i < BT * FIN)
                    xst[q] = __ldcg(&x[((b0 + i / FIN) * TT + (t + 1)) * FIN + (i % FIN)]);
            }
        }

        u64 a01 = 0, a23 = 0;               // packed accumulators (r0,r1)(r2,r3)
        const ulonglong2* ub = (const ulonglong2*)(buf[cb] + k0);

        #pragma unroll
        for (int q = 0; q < KREG; ++q) {            // register weights
            ulonglong2 av = ub[q];                  // LDS.128, warp-uniform
            u64 wp = dup2(w[q]);
            ffma2(a01, av.x, wp);
            ffma2(a23, av.y, wp);
        }
        if (KSM > 0) {                               // smem weights
            const float* wsp = ws + (p * KSM) * H + j;
            #pragma unroll 8
            for (int s = 0; s < KSM; ++s) {
                ulonglong2 av = ub[KREG + s];
                u64 wp = dup2(wsp[s * H]);
                ffma2(a01, av.x, wp);
                ffma2(a23, av.y, wp);
            }
        }

        float2 f01 = *(float2*)&a01;
        float2 f23 = *(float2*)&a23;
        part[p][0][j] = f01.x;
        part[p][1][j] = f01.y;
        part[p][2][j] = f23.x;
        part[p][3][j] = f23.y;
        if (t + 1 < TT) {
            #pragma unroll
            for (int q = 0; q < CNTX; ++q) {
                int i = tid + q * THREADS;
                if (i < BT * FIN)
                    ((float*)buf[nb])[(i % FIN) * 4 + (i / FIN)] = xst[q];
            }
        }
        __syncthreads();

        #pragma unroll
        for (int q = 0; q < CNT; ++q) {
            int e = tid + q * THREADS;
            if (e < BT * H) {
                int r = e / H, jj = e % H;
                float s = bj[q];
                #pragma unroll
                for (int pp = 0; pp < P; ++pp) s += part[pp][r][jj];
                s = fmaxf(s, 0.f);
                ((float*)buf[nb])[(FIN + jj) * 4 + r] = s;
                __stcg(&hout[((b0 + r) * TT + t) * H + jj], s);
            }
        }
        __syncthreads();
        cb = nb;
    }
}

extern "C" void kernel_launch(void* const* d_in, const int* in_sizes, int n_in,
                              void* d_out, int out_size)
{
    (void)in_sizes; (void)n_in; (void)out_size;

    const float* x   = (const float*)d_in[0];
    const float* Wx1 = (const float*)d_in[1];
    const float* Wh1 = (const float*)d_in[2];
    const float* b1  = (const float*)d_in[3];
    const float* Wx2 = (const float*)d_in[4];
    const float* Wh2 = (const float*)d_in[5];
    const float* b2  = (const float*)d_in[6];
    const float* Wx3 = (const float*)d_in[7];
    const float* Wh3 = (const float*)d_in[8];
    const float* b3  = (const float*)d_in[9];
    const float* Wx4 = (const float*)d_in[10];
    const float* Wh4 = (const float*)d_in[11];
    const float* b4  = (const float*)d_in[12];
    const float* Wd  = (const float*)d_in[13];
    const float* bd  = (const float*)d_in[14];
    float* out = (float*)d_out;

    float *bufA = nullptr, *bufB = nullptr;
    cudaGetSymbolAddress((void**)&bufA, g_bufA);
    cudaGetSymbolAddress((void**)&bufB, g_bufB);

    const dim3 grid(BB / 4);   // 128 CTAs

    // Dynamic smem (weight overflow):
    //   L2 (movdup P=2): 2*96*256*4 = 196608 B
    //   L3 (scalar):     4*16*128*4 = 32768 B
    constexpr int DynL2 = 2 * 96 * 256 * 4;
    constexpr int DynL3 = 4 * 16 * 128 * 4;
    cudaFuncSetAttribute(rnn_layer_md<128, 256, 2, 96, 512>,
                         cudaFuncAttributeMaxDynamicSharedMemorySize, DynL2);
    cudaFuncSetAttribute(rnn_layer<256, 128, 4, 80, 512, false>,
                         cudaFuncAttributeMaxDynamicSharedMemorySize, DynL3);

    // L1: scalar, 512 thr, P=4, KS=48 all in regs (measured best)
    rnn_layer<64, 128, 4, 48, 512, false><<<grid, 512, 0>>>(
        x, Wx1, Wh1, b1, bufA, nullptr, nullptr, nullptr);
    // L2: movdup FFMA2, 512 thr, P=2, KREG=96 + 96 smem rows (4 warps/SMSP)
    rnn_layer_md<128, 256, 2, 96, 512><<<grid, 512, DynL2>>>(
        bufA, Wx2, Wh2, b2, bufB);
    // L3: scalar, 512 thr, P=4, 80 regs + 16 smem rows (measured best)
    rnn_layer<256, 128, 4, 80, 512, false><<<grid, 512, DynL3>>>(
        bufB, Wx3, Wh3, b3, bufA, nullptr, nullptr, nullptr);
    // L4: scalar, 256 thr, P=4, KS=48 all in regs, fused dense (183us measured)
    rnn_layer<128, 64, 4, 48, 256, true><<<grid, 256, 0>>>(
        bufA, Wx4, Wh4, b4, nullptr, Wd, bd, out);
}